// round 2
// baseline (speedup 1.0000x reference)
#include <cuda_runtime.h>
#include <cuda_bf16.h>
#include <cstdint>

// Problem constants (match reference setup_inputs)
constexpr int B_ = 2;
constexpr int H_ = 16;
constexpr int S_ = 2048;
constexpr int D_ = 1024;     // d_model
constexpr int DK_ = 64;      // head dim

// -------------------- device scratch (no allocations allowed) --------------------
__device__ float g_Q[(size_t)B_ * H_ * S_ * DK_];    // [B,H,S,Dk]
__device__ float g_K[(size_t)B_ * H_ * S_ * DK_];
__device__ float g_V[(size_t)B_ * H_ * S_ * DK_];
__device__ float g_ctx[(size_t)B_ * S_ * D_];        // [B,S,D] (heads concatenated)

// ==================== GEMM: C = A @ W + bias ====================
// A: [M=4096, K=1024] row-major, W: [1024,1024] row-major, bias [1024].
// Tile 128x64, BK=16, 256 threads, 8x4 micro-tile per thread.
constexpr int GBM = 128, GBN = 64, GBK = 16;

// TGT: 0 -> g_Q, 1 -> g_K, 2 -> g_V (head-split epilogue layout)
template <int TGT>
__global__ __launch_bounds__(256) void gemm_qkv_kernel(const float* __restrict__ A,
                                                       const float* __restrict__ W,
                                                       const float* __restrict__ bias) {
    __shared__ __align__(16) float As[GBK][GBM + 4];
    __shared__ __align__(16) float Bs[GBK][GBN + 4];

    const int tid = threadIdx.x;
    const int tx = tid & 15, ty = tid >> 4;
    const int m0 = blockIdx.y * GBM, n0 = blockIdx.x * GBN;

    float acc[8][4];
#pragma unroll
    for (int i = 0; i < 8; i++)
#pragma unroll
        for (int j = 0; j < 4; j++) acc[i][j] = 0.f;

    for (int k0 = 0; k0 < D_; k0 += GBK) {
#pragma unroll
        for (int r = 0; r < 2; r++) {
            int idx = tid + r * 256;          // 512 float4 = 2048 floats (A tile)
            int m = idx >> 2, kk = (idx & 3) << 2;
            float4 a = *(const float4*)(A + (size_t)(m0 + m) * D_ + k0 + kk);
            As[kk + 0][m] = a.x; As[kk + 1][m] = a.y;
            As[kk + 2][m] = a.z; As[kk + 3][m] = a.w;
        }
        {
            int kk = tid >> 4, n4 = (tid & 15) << 2;   // B tile 16x64
            *(float4*)&Bs[kk][n4] = *(const float4*)(W + (size_t)(k0 + kk) * D_ + n0 + n4);
        }
        __syncthreads();

#pragma unroll
        for (int k = 0; k < GBK; k++) {
            float a[8], b[4];
#pragma unroll
            for (int i = 0; i < 8; i++) a[i] = As[k][ty * 8 + i];
#pragma unroll
            for (int j = 0; j < 4; j++) b[j] = Bs[k][tx * 4 + j];
#pragma unroll
            for (int i = 0; i < 8; i++)
#pragma unroll
                for (int j = 0; j < 4; j++) acc[i][j] = fmaf(a[i], b[j], acc[i][j]);
        }
        __syncthreads();
    }

    // epilogue: head-split layout out[((b*H+h)*S + s)*64 + d]
    const int n = n0 + tx * 4;
    const float4 bv = *(const float4*)(bias + n);
    const int h = n >> 6;       // constant per block (GBN == 64)
    const int dcol = n & 63;
    float* dst;
    if constexpr (TGT == 0) dst = g_Q;
    else if constexpr (TGT == 1) dst = g_K;
    else dst = g_V;

#pragma unroll
    for (int i = 0; i < 8; i++) {
        int m = m0 + ty * 8 + i;
        int b = m >> 11, s = m & (S_ - 1);
        float4 o;
        o.x = acc[i][0] + bv.x; o.y = acc[i][1] + bv.y;
        o.z = acc[i][2] + bv.z; o.w = acc[i][3] + bv.w;
        *(float4*)(dst + ((size_t)((b * H_ + h) * S_ + s)) * DK_ + dcol) = o;
    }
}

// Output projection: out = ctx @ Wo + bo  (plain layout)
__global__ __launch_bounds__(256) void gemm_out_kernel(const float* __restrict__ W,
                                                       const float* __restrict__ bias,
                                                       float* __restrict__ outp) {
    __shared__ __align__(16) float As[GBK][GBM + 4];
    __shared__ __align__(16) float Bs[GBK][GBN + 4];

    const int tid = threadIdx.x;
    const int tx = tid & 15, ty = tid >> 4;
    const int m0 = blockIdx.y * GBM, n0 = blockIdx.x * GBN;
    const float* A = g_ctx;

    float acc[8][4];
#pragma unroll
    for (int i = 0; i < 8; i++)
#pragma unroll
        for (int j = 0; j < 4; j++) acc[i][j] = 0.f;

    for (int k0 = 0; k0 < D_; k0 += GBK) {
#pragma unroll
        for (int r = 0; r < 2; r++) {
            int idx = tid + r * 256;
            int m = idx >> 2, kk = (idx & 3) << 2;
            float4 a = *(const float4*)(A + (size_t)(m0 + m) * D_ + k0 + kk);
            As[kk + 0][m] = a.x; As[kk + 1][m] = a.y;
            As[kk + 2][m] = a.z; As[kk + 3][m] = a.w;
        }
        {
            int kk = tid >> 4, n4 = (tid & 15) << 2;
            *(float4*)&Bs[kk][n4] = *(const float4*)(W + (size_t)(k0 + kk) * D_ + n0 + n4);
        }
        __syncthreads();

#pragma unroll
        for (int k = 0; k < GBK; k++) {
            float a[8], b[4];
#pragma unroll
            for (int i = 0; i < 8; i++) a[i] = As[k][ty * 8 + i];
#pragma unroll
            for (int j = 0; j < 4; j++) b[j] = Bs[k][tx * 4 + j];
#pragma unroll
            for (int i = 0; i < 8; i++)
#pragma unroll
                for (int j = 0; j < 4; j++) acc[i][j] = fmaf(a[i], b[j], acc[i][j]);
        }
        __syncthreads();
    }

    const int n = n0 + tx * 4;
    const float4 bv = *(const float4*)(bias + n);
#pragma unroll
    for (int i = 0; i < 8; i++) {
        int m = m0 + ty * 8 + i;
        float4 o;
        o.x = acc[i][0] + bv.x; o.y = acc[i][1] + bv.y;
        o.z = acc[i][2] + bv.z; o.w = acc[i][3] + bv.w;
        *(float4*)(outp + (size_t)m * D_ + n) = o;
    }
}

// ==================== Flash attention ====================
// grid: (S/64 q-tiles, B*H). 256 threads.
// Q tile 64 rows, K tile 32 keys per iteration, Dk=64.
constexpr int AQ = 64;   // q rows per block
constexpr int AK = 32;   // keys per tile

__global__ __launch_bounds__(256) void attn_kernel(const int* __restrict__ mask) {
    __shared__ __align__(16) float Qs[AQ][68];        // [row][d], pre-scaled
    __shared__ __align__(16) float KsT[DK_][AK];      // [d][key]
    __shared__ __align__(16) float Vs[AK][68];        // [key][d]
    __shared__ __align__(16) float Ps[AQ][36];        // [row][key]
    __shared__ float row_m[AQ], row_l[AQ], row_corr[AQ];

    const int tid = threadIdx.x;
    const int bh = blockIdx.y, b = bh >> 4, h = bh & 15;
    const int qt = blockIdx.x;

    const float* Qg = g_Q + ((size_t)bh * S_ + qt * AQ) * DK_;
    const float* Kg = g_K + (size_t)bh * S_ * DK_;
    const float* Vg = g_V + (size_t)bh * S_ * DK_;
    const int* mrow = mask + b * S_;

    // load Q tile (scaled by 1/sqrt(Dk) = 0.125)
#pragma unroll
    for (int r = 0; r < 4; r++) {
        int idx = tid + r * 256;               // 1024 float4
        int row = idx >> 4, d4 = (idx & 15) << 2;
        float4 q = *(const float4*)(Qg + (size_t)row * DK_ + d4);
        q.x *= 0.125f; q.y *= 0.125f; q.z *= 0.125f; q.w *= 0.125f;
        *(float4*)&Qs[row][d4] = q;
    }
    if (tid < AQ) {
        row_m[tid] = __int_as_float(0xff800000);   // -inf
        row_l[tid] = 0.f;
    }

    const int tx = tid & 15, ty = tid >> 4;    // O phase: rows 4ty+i, d-cols 4tx+j
    const int sx = tid & 7, sy = tid >> 3;     // score phase: rows 2sy+i, keys 4sx+j

    float o[4][4];
#pragma unroll
    for (int i = 0; i < 4; i++)
#pragma unroll
        for (int j = 0; j < 4; j++) o[i][j] = 0.f;

    __syncthreads();

    for (int kt = 0; kt < S_ / AK; kt++) {
        // ---- load K (transposed) and V tiles ----
#pragma unroll
        for (int r = 0; r < 2; r++) {
            int idx = tid + r * 256;           // 512 float4
            int s = idx & 31, d4 = idx >> 5;
            float4 kv = *(const float4*)(Kg + (size_t)(kt * AK + s) * DK_ + d4 * 4);
            KsT[d4 * 4 + 0][s] = kv.x; KsT[d4 * 4 + 1][s] = kv.y;
            KsT[d4 * 4 + 2][s] = kv.z; KsT[d4 * 4 + 3][s] = kv.w;
        }
#pragma unroll
        for (int r = 0; r < 2; r++) {
            int idx = tid + r * 256;
            int s = idx >> 4, d4 = (idx & 15) << 2;
            *(float4*)&Vs[s][d4] = *(const float4*)(Vg + (size_t)(kt * AK + s) * DK_ + d4);
        }
        __syncthreads();   // (A)

        // ---- scores sc[2][4]: rows 2sy+i, keys 4sx+j ----
        float sc[2][4];
#pragma unroll
        for (int i = 0; i < 2; i++)
#pragma unroll
            for (int j = 0; j < 4; j++) sc[i][j] = 0.f;

#pragma unroll
        for (int d4 = 0; d4 < 16; d4++) {
            float q[2][4];
#pragma unroll
            for (int i = 0; i < 2; i++) {
                float4 t = *(const float4*)&Qs[2 * sy + i][d4 * 4];
                q[i][0] = t.x; q[i][1] = t.y; q[i][2] = t.z; q[i][3] = t.w;
            }
#pragma unroll
            for (int u = 0; u < 4; u++) {
                float4 t = *(const float4*)&KsT[d4 * 4 + u][sx * 4];
                float kv[4] = {t.x, t.y, t.z, t.w};
#pragma unroll
                for (int i = 0; i < 2; i++)
#pragma unroll
                    for (int j = 0; j < 4; j++)
                        sc[i][j] = fmaf(q[i][u], kv[j], sc[i][j]);
            }
        }

        // ---- mask ----
#pragma unroll
        for (int j = 0; j < 4; j++) {
            int mv = mrow[kt * AK + sx * 4 + j];
            if (mv == 0) { sc[0][j] = -1e9f; sc[1][j] = -1e9f; }
        }

        // ---- row max (reduce over 8 lanes sharing sy) ----
        float lm[2];
#pragma unroll
        for (int i = 0; i < 2; i++) {
            lm[i] = fmaxf(fmaxf(sc[i][0], sc[i][1]), fmaxf(sc[i][2], sc[i][3]));
        }
#pragma unroll
        for (int off = 4; off > 0; off >>= 1) {
            lm[0] = fmaxf(lm[0], __shfl_xor_sync(0xffffffffu, lm[0], off));
            lm[1] = fmaxf(lm[1], __shfl_xor_sync(0xffffffffu, lm[1], off));
        }
        if (sx == 0) {
#pragma unroll
            for (int i = 0; i < 2; i++) {
                int r = 2 * sy + i;
                float mold = row_m[r];
                float mn = fmaxf(mold, lm[i]);
                row_m[r] = mn;
                row_corr[r] = __expf(mold - mn);   // exp(-inf)=0 on first tile
            }
        }
        __syncthreads();   // (B)

        // ---- p = exp(sc - m_new), write to Ps, accumulate row sums ----
        float mn0 = row_m[2 * sy], mn1 = row_m[2 * sy + 1];
        float rs[2] = {0.f, 0.f};
        float p0[4], p1[4];
#pragma unroll
        for (int j = 0; j < 4; j++) {
            p0[j] = __expf(sc[0][j] - mn0);
            p1[j] = __expf(sc[1][j] - mn1);
            rs[0] += p0[j]; rs[1] += p1[j];
        }
        *(float4*)&Ps[2 * sy + 0][sx * 4] = make_float4(p0[0], p0[1], p0[2], p0[3]);
        *(float4*)&Ps[2 * sy + 1][sx * 4] = make_float4(p1[0], p1[1], p1[2], p1[3]);
#pragma unroll
        for (int off = 4; off > 0; off >>= 1) {
            rs[0] += __shfl_xor_sync(0xffffffffu, rs[0], off);
            rs[1] += __shfl_xor_sync(0xffffffffu, rs[1], off);
        }
        if (sx == 0) {
#pragma unroll
            for (int i = 0; i < 2; i++) {
                int r = 2 * sy + i;
                row_l[r] = row_l[r] * row_corr[r] + rs[i];
            }
        }
        __syncthreads();   // (C)

        // ---- O update: rescale + P @ V ----
        float corr[4];
#pragma unroll
        for (int i = 0; i < 4; i++) corr[i] = row_corr[4 * ty + i];
#pragma unroll
        for (int i = 0; i < 4; i++)
#pragma unroll
            for (int j = 0; j < 4; j++) o[i][j] *= corr[i];

#pragma unroll
        for (int k4 = 0; k4 < 8; k4++) {
            float p[4][4];
#pragma unroll
            for (int i = 0; i < 4; i++) {
                float4 t = *(const float4*)&Ps[4 * ty + i][k4 * 4];
                p[i][0] = t.x; p[i][1] = t.y; p[i][2] = t.z; p[i][3] = t.w;
            }
#pragma unroll
            for (int u = 0; u < 4; u++) {
                float4 t = *(const float4*)&Vs[k4 * 4 + u][tx * 4];
                float vv[4] = {t.x, t.y, t.z, t.w};
#pragma unroll
                for (int i = 0; i < 4; i++)
#pragma unroll
                    for (int j = 0; j < 4; j++)
                        o[i][j] = fmaf(p[i][u], vv[j], o[i][j]);
            }
        }
        __syncthreads();   // (D)
    }

    // ---- epilogue: normalize and write ctx[(b*S + qrow)*D + h*64 + dcol] ----
    float inv[4];
#pragma unroll
    for (int i = 0; i < 4; i++) inv[i] = 1.f / row_l[4 * ty + i];

    float* dst = g_ctx + ((size_t)(b * S_ + qt * AQ)) * D_ + h * DK_;
#pragma unroll
    for (int i = 0; i < 4; i++) {
        float4 ov = make_float4(o[i][0] * inv[i], o[i][1] * inv[i],
                                o[i][2] * inv[i], o[i][3] * inv[i]);
        *(float4*)(dst + (size_t)(4 * ty + i) * D_ + tx * 4) = ov;
    }
}

// ==================== launch ====================
extern "C" void kernel_launch(void* const* d_in, const int* in_sizes, int n_in,
                              void* d_out, int out_size) {
    const float* query = (const float*)d_in[0];
    const float* key   = (const float*)d_in[1];
    const float* value = (const float*)d_in[2];
    const int*   mask  = (const int*)d_in[3];
    const float* Wq = (const float*)d_in[4];
    const float* bq = (const float*)d_in[5];
    const float* Wk = (const float*)d_in[6];
    const float* bk = (const float*)d_in[7];
    const float* Wv = (const float*)d_in[8];
    const float* bv = (const float*)d_in[9];
    const float* Wo = (const float*)d_in[10];
    const float* bo = (const float*)d_in[11];
    float* out = (float*)d_out;

    dim3 gg(D_ / GBN, (B_ * S_) / GBM);   // (16, 32)
    gemm_qkv_kernel<0><<<gg, 256>>>(query, Wq, bq);
    gemm_qkv_kernel<1><<<gg, 256>>>(key, Wk, bk);
    gemm_qkv_kernel<2><<<gg, 256>>>(value, Wv, bv);

    dim3 ga(S_ / AQ, B_ * H_);            // (32, 32)
    attn_kernel<<<ga, 256>>>(mask);

    gemm_out_kernel<<<gg, 256>>>(Wo, bo, out);
}

// round 5
// speedup vs baseline: 1.3546x; 1.3546x over previous
#include <cuda_runtime.h>
#include <cuda_bf16.h>
#include <cstdint>

// Problem constants (match reference setup_inputs)
constexpr int B_ = 2;
constexpr int H_ = 16;
constexpr int S_ = 2048;
constexpr int D_ = 1024;     // d_model
constexpr int DK_ = 64;      // head dim
constexpr int M_ = B_ * S_;  // 4096 rows in all GEMMs

// ==================== PTX helpers (sm_80-baseline only!) ====================
__device__ __forceinline__ uint32_t smem_to_u32(const void* p) {
    uint32_t a;
    asm("{ .reg .u64 t; cvta.to.shared.u64 t, %1; cvt.u32.u64 %0, t; }" : "=r"(a) : "l"(p));
    return a;
}
__device__ __forceinline__ void cp_async16(uint32_t dst, const void* src) {
    asm volatile("cp.async.cg.shared.global [%0], [%1], 16;" :: "r"(dst), "l"(src));
}
__device__ __forceinline__ void cp_commit() {
    asm volatile("cp.async.commit_group;");
}
template <int N>
__device__ __forceinline__ void cp_wait() {
    asm volatile("cp.async.wait_group %0;" :: "n"(N));
}
__device__ __forceinline__ void ldm_x4(uint32_t& r0, uint32_t& r1, uint32_t& r2, uint32_t& r3,
                                       uint32_t addr) {
    asm volatile("ldmatrix.sync.aligned.m8n8.x4.shared.b16 {%0,%1,%2,%3}, [%4];"
                 : "=r"(r0), "=r"(r1), "=r"(r2), "=r"(r3) : "r"(addr));
}
__device__ __forceinline__ void mma_bf16(float* c, const uint32_t* a, const uint32_t* b) {
    asm volatile(
        "mma.sync.aligned.m16n8k16.row.col.f32.bf16.bf16.f32 "
        "{%0,%1,%2,%3}, {%4,%5,%6,%7}, {%8,%9}, {%0,%1,%2,%3};"
        : "+f"(c[0]), "+f"(c[1]), "+f"(c[2]), "+f"(c[3])
        : "r"(a[0]), "r"(a[1]), "r"(a[2]), "r"(a[3]), "r"(b[0]), "r"(b[1]));
}

// -------------------- device scratch (no allocations allowed) --------------------
__device__ float g_Q[(size_t)B_ * H_ * S_ * DK_];    // [B,H,S,Dk]
__device__ float g_K[(size_t)B_ * H_ * S_ * DK_];
__device__ float g_V[(size_t)B_ * H_ * S_ * DK_];
__device__ float g_ctx[(size_t)B_ * S_ * D_];        // [B,S,D]

// bf16 hi/lo splits. actH/L[0..2] = query/key/value activations [M,K] row-major.
__device__ __nv_bfloat16 g_actH[3][(size_t)M_ * D_];
__device__ __nv_bfloat16 g_actL[3][(size_t)M_ * D_];
__device__ __nv_bfloat16 g_ctxH[(size_t)M_ * D_];
__device__ __nv_bfloat16 g_ctxL[(size_t)M_ * D_];
// transposed weights [N,K] (GEMM is D = A @ B^T, both K-major -> row.col mma)
__device__ __nv_bfloat16 g_wTH[4][(size_t)D_ * D_];
__device__ __nv_bfloat16 g_wTL[4][(size_t)D_ * D_];

// ==================== conversion kernels ====================
__global__ __launch_bounds__(256) void conv_hl_kernel(const float* __restrict__ src, int which) {
    __nv_bfloat16* hi;
    __nv_bfloat16* lo;
    if (which < 3) { hi = g_actH[which]; lo = g_actL[which]; }
    else           { hi = g_ctxH;        lo = g_ctxL;        src = g_ctx; }

    int i = blockIdx.x * blockDim.x + threadIdx.x;   // float4 index
    float4 v = ((const float4*)src)[i];
    float f[4] = {v.x, v.y, v.z, v.w};
    __nv_bfloat16 h[4], l[4];
#pragma unroll
    for (int j = 0; j < 4; j++) {
        h[j] = __float2bfloat16(f[j]);
        l[j] = __float2bfloat16(f[j] - __bfloat162float(h[j]));
    }
    ((__nv_bfloat162*)hi)[i * 2 + 0] = __nv_bfloat162(h[0], h[1]);
    ((__nv_bfloat162*)hi)[i * 2 + 1] = __nv_bfloat162(h[2], h[3]);
    ((__nv_bfloat162*)lo)[i * 2 + 0] = __nv_bfloat162(l[0], l[1]);
    ((__nv_bfloat162*)lo)[i * 2 + 1] = __nv_bfloat162(l[2], l[3]);
}

// W [K,N] fp32 -> transposed hi/lo bf16 [N,K]
__global__ __launch_bounds__(256) void conv_wT_kernel(const float* __restrict__ W, int which) {
    __shared__ float t[32][33];
    const int n0 = blockIdx.x * 32, k0 = blockIdx.y * 32;
    const int tx = threadIdx.x, ty = threadIdx.y;     // block (32,8)
#pragma unroll
    for (int r = 0; r < 32; r += 8)
        t[ty + r][tx] = W[(size_t)(k0 + ty + r) * D_ + n0 + tx];
    __syncthreads();
    __nv_bfloat16* hi = g_wTH[which];
    __nv_bfloat16* lo = g_wTL[which];
#pragma unroll
    for (int r = 0; r < 32; r += 8) {
        float v = t[tx][ty + r];
        __nv_bfloat16 h = __float2bfloat16(v);
        __nv_bfloat16 l = __float2bfloat16(v - __bfloat162float(h));
        size_t o = (size_t)(n0 + ty + r) * D_ + k0 + tx;
        hi[o] = h; lo[o] = l;
    }
}

// ==================== mma.sync GEMM (3x bf16 split) ====================
// C[4096,1024] = A @ W + bias. CTA 128x128, BK=32, 8 warps (warp tile 32x64),
// cp.async double-buffered. TGT 0..2 -> head-split g_Q/K/V, TGT 3 -> outp.
constexpr int BM = 128, BN = 128, BK = 32;
constexpr int TPAD = 40;                        // padded row length in bf16 (80B)
constexpr int TILE_B = 128 * TPAD * 2;          // 10240 B per operand tile
constexpr int STAGE_B = 4 * TILE_B;             // Ahi,Alo,Bhi,Blo = 40960 B
constexpr int GSMEM = 2 * STAGE_B;              // 81920 B
constexpr int NC = D_ / BK;                     // 32 k-chunks

template <int TGT>
__global__ __launch_bounds__(256, 2) void gemm_mma_kernel(const float* __restrict__ bias,
                                                          float* __restrict__ outp) {
    extern __shared__ __align__(128) char sm[];
    const uint32_t smbase = smem_to_u32(sm);
    const int tid = threadIdx.x, wid = tid >> 5, lane = tid & 31;
    const int m0 = blockIdx.y * BM, n0 = blockIdx.x * BN;
    const int wm = (wid & 3) * 32, wn = (wid >> 2) * 64;

    const __nv_bfloat16* Ah;
    const __nv_bfloat16* Al;
    if constexpr (TGT < 3) { Ah = g_actH[TGT]; Al = g_actL[TGT]; }
    else                   { Ah = g_ctxH;      Al = g_ctxL;      }
    const __nv_bfloat16* Bh = g_wTH[TGT];
    const __nv_bfloat16* Bl = g_wTL[TGT];

    float acc[2][8][4];
#pragma unroll
    for (int i = 0; i < 2; i++)
#pragma unroll
        for (int j = 0; j < 8; j++)
#pragma unroll
            for (int q = 0; q < 4; q++) acc[i][j][q] = 0.f;

    // per-thread load coords (8 x 16B per chunk; tile = i>>9, row = (i&511)>>2, c16 = i&3)
    auto issue_load = [&](int c) {
        const int s = c & 1, k0 = c * BK;
        const uint32_t st = smbase + s * STAGE_B;
#pragma unroll
        for (int t = 0; t < 8; t++) {
            int i = tid + t * 256;
            int tile = i >> 9, rem = i & 511, row = rem >> 2, cc = rem & 3;
            const __nv_bfloat16* src;
            if (tile == 0)      src = Ah + (size_t)(m0 + row) * D_ + k0 + cc * 8;
            else if (tile == 1) src = Al + (size_t)(m0 + row) * D_ + k0 + cc * 8;
            else if (tile == 2) src = Bh + (size_t)(n0 + row) * D_ + k0 + cc * 8;
            else                src = Bl + (size_t)(n0 + row) * D_ + k0 + cc * 8;
            cp_async16(st + tile * TILE_B + (row * TPAD + cc * 8) * 2, src);
        }
        cp_commit();
    };

    issue_load(0);

    for (int c = 0; c < NC; c++) {
        if (c + 1 < NC) { issue_load(c + 1); cp_wait<1>(); }
        else            { cp_wait<0>(); }
        __syncthreads();

        const uint32_t st = smbase + (c & 1) * STAGE_B;
#pragma unroll
        for (int k16 = 0; k16 < BK; k16 += 16) {
            // A fragments (hi & lo), 2 m-tiles
            uint32_t a_hi[2][4], a_lo[2][4];
            const int arow = wm + (lane & 15);
            const int acol = k16 + (lane >> 4) * 8;
#pragma unroll
            for (int i = 0; i < 2; i++) {
                uint32_t off = ((arow + i * 16) * TPAD + acol) * 2;
                ldm_x4(a_hi[i][0], a_hi[i][1], a_hi[i][2], a_hi[i][3], st + off);
                ldm_x4(a_lo[i][0], a_lo[i][1], a_lo[i][2], a_lo[i][3], st + TILE_B + off);
            }
            // B fragment pairs: 4 x (2 n-tiles)
            const int brow_base = wn + ((lane >> 4) & 1) * 8 + (lane & 7);
            const int bcol = k16 + ((lane >> 3) & 1) * 8;
#pragma unroll
            for (int jj = 0; jj < 4; jj++) {
                uint32_t off = ((brow_base + jj * 16) * TPAD + bcol) * 2;
                uint32_t bh[4], bl[4];
                ldm_x4(bh[0], bh[1], bh[2], bh[3], st + 2 * TILE_B + off);
                ldm_x4(bl[0], bl[1], bl[2], bl[3], st + 3 * TILE_B + off);
#pragma unroll
                for (int i = 0; i < 2; i++) {
                    mma_bf16(acc[i][2 * jj + 0], a_hi[i], bh + 0);
                    mma_bf16(acc[i][2 * jj + 0], a_lo[i], bh + 0);
                    mma_bf16(acc[i][2 * jj + 0], a_hi[i], bl + 0);
                    mma_bf16(acc[i][2 * jj + 1], a_hi[i], bh + 2);
                    mma_bf16(acc[i][2 * jj + 1], a_lo[i], bh + 2);
                    mma_bf16(acc[i][2 * jj + 1], a_hi[i], bl + 2);
                }
            }
        }
        __syncthreads();
    }

    // ---- epilogue: C frag (m16n8): c0,c1 -> row r=lane/4, cols 2(lane%4)+{0,1}; c2,c3 -> row r+8
    const int tr = lane >> 2, tc = (lane & 3) * 2;
#pragma unroll
    for (int i = 0; i < 2; i++) {
#pragma unroll
        for (int hh = 0; hh < 2; hh++) {
            const int m = m0 + wm + i * 16 + tr + hh * 8;
            float* p;
            if constexpr (TGT < 3) {
                float* dst;
                if constexpr (TGT == 0) dst = g_Q;
                else if constexpr (TGT == 1) dst = g_K;
                else dst = g_V;
                const int hd = (n0 + wn) >> 6;          // head index (warp-constant)
                const int b = m >> 11, sq = m & (S_ - 1);
                p = dst + ((size_t)((b * H_ + hd) * S_ + sq)) * DK_ + ((wn + tc) & 63);
            } else {
                p = outp + (size_t)m * D_ + n0 + wn + tc;
            }
#pragma unroll
            for (int j = 0; j < 8; j++) {
                const int n = n0 + wn + j * 8 + tc;
                float2 o;
                o.x = acc[i][j][hh * 2 + 0] + bias[n];
                o.y = acc[i][j][hh * 2 + 1] + bias[n + 1];
                *(float2*)(p + j * 8) = o;
            }
        }
    }
}

// ==================== Flash attention (fp32 SIMT, unchanged) ====================
constexpr int AQ = 64;   // q rows per block
constexpr int AK = 32;   // keys per tile

__global__ __launch_bounds__(256) void attn_kernel(const int* __restrict__ mask) {
    __shared__ __align__(16) float Qs[AQ][68];
    __shared__ __align__(16) float KsT[DK_][AK];
    __shared__ __align__(16) float Vs[AK][68];
    __shared__ __align__(16) float Ps[AQ][36];
    __shared__ float row_m[AQ], row_l[AQ], row_corr[AQ];

    const int tid = threadIdx.x;
    const int bh = blockIdx.y, b = bh >> 4, h = bh & 15;
    const int qt = blockIdx.x;

    const float* Qg = g_Q + ((size_t)bh * S_ + qt * AQ) * DK_;
    const float* Kg = g_K + (size_t)bh * S_ * DK_;
    const float* Vg = g_V + (size_t)bh * S_ * DK_;
    const int* mrow = mask + b * S_;

#pragma unroll
    for (int r = 0; r < 4; r++) {
        int idx = tid + r * 256;
        int row = idx >> 4, d4 = (idx & 15) << 2;
        float4 q = *(const float4*)(Qg + (size_t)row * DK_ + d4);
        q.x *= 0.125f; q.y *= 0.125f; q.z *= 0.125f; q.w *= 0.125f;
        *(float4*)&Qs[row][d4] = q;
    }
    if (tid < AQ) {
        row_m[tid] = __int_as_float(0xff800000);
        row_l[tid] = 0.f;
    }

    const int tx = tid & 15, ty = tid >> 4;
    const int sx = tid & 7, sy = tid >> 3;

    float o[4][4];
#pragma unroll
    for (int i = 0; i < 4; i++)
#pragma unroll
        for (int j = 0; j < 4; j++) o[i][j] = 0.f;

    __syncthreads();

    for (int kt = 0; kt < S_ / AK; kt++) {
#pragma unroll
        for (int r = 0; r < 2; r++) {
            int idx = tid + r * 256;
            int s = idx & 31, d4 = idx >> 5;
            float4 kv = *(const float4*)(Kg + (size_t)(kt * AK + s) * DK_ + d4 * 4);
            KsT[d4 * 4 + 0][s] = kv.x; KsT[d4 * 4 + 1][s] = kv.y;
            KsT[d4 * 4 + 2][s] = kv.z; KsT[d4 * 4 + 3][s] = kv.w;
        }
#pragma unroll
        for (int r = 0; r < 2; r++) {
            int idx = tid + r * 256;
            int s = idx >> 4, d4 = (idx & 15) << 2;
            *(float4*)&Vs[s][d4] = *(const float4*)(Vg + (size_t)(kt * AK + s) * DK_ + d4);
        }
        __syncthreads();

        float sc[2][4];
#pragma unroll
        for (int i = 0; i < 2; i++)
#pragma unroll
            for (int j = 0; j < 4; j++) sc[i][j] = 0.f;

#pragma unroll
        for (int d4 = 0; d4 < 16; d4++) {
            float q[2][4];
#pragma unroll
            for (int i = 0; i < 2; i++) {
                float4 t = *(const float4*)&Qs[2 * sy + i][d4 * 4];
                q[i][0] = t.x; q[i][1] = t.y; q[i][2] = t.z; q[i][3] = t.w;
            }
#pragma unroll
            for (int u = 0; u < 4; u++) {
                float4 t = *(const float4*)&KsT[d4 * 4 + u][sx * 4];
                float kv[4] = {t.x, t.y, t.z, t.w};
#pragma unroll
                for (int i = 0; i < 2; i++)
#pragma unroll
                    for (int j = 0; j < 4; j++)
                        sc[i][j] = fmaf(q[i][u], kv[j], sc[i][j]);
            }
        }

#pragma unroll
        for (int j = 0; j < 4; j++) {
            int mv = mrow[kt * AK + sx * 4 + j];
            if (mv == 0) { sc[0][j] = -1e9f; sc[1][j] = -1e9f; }
        }

        float lm[2];
#pragma unroll
        for (int i = 0; i < 2; i++)
            lm[i] = fmaxf(fmaxf(sc[i][0], sc[i][1]), fmaxf(sc[i][2], sc[i][3]));
#pragma unroll
        for (int off = 4; off > 0; off >>= 1) {
            lm[0] = fmaxf(lm[0], __shfl_xor_sync(0xffffffffu, lm[0], off));
            lm[1] = fmaxf(lm[1], __shfl_xor_sync(0xffffffffu, lm[1], off));
        }
        if (sx == 0) {
#pragma unroll
            for (int i = 0; i < 2; i++) {
                int r = 2 * sy + i;
                float mold = row_m[r];
                float mn = fmaxf(mold, lm[i]);
                row_m[r] = mn;
                row_corr[r] = __expf(mold - mn);
            }
        }
        __syncthreads();

        float mn0 = row_m[2 * sy], mn1 = row_m[2 * sy + 1];
        float rs[2] = {0.f, 0.f};
        float p0[4], p1[4];
#pragma unroll
        for (int j = 0; j < 4; j++) {
            p0[j] = __expf(sc[0][j] - mn0);
            p1[j] = __expf(sc[1][j] - mn1);
            rs[0] += p0[j]; rs[1] += p1[j];
        }
        *(float4*)&Ps[2 * sy + 0][sx * 4] = make_float4(p0[0], p0[1], p0[2], p0[3]);
        *(float4*)&Ps[2 * sy + 1][sx * 4] = make_float4(p1[0], p1[1], p1[2], p1[3]);
#pragma unroll
        for (int off = 4; off > 0; off >>= 1) {
            rs[0] += __shfl_xor_sync(0xffffffffu, rs[0], off);
            rs[1] += __shfl_xor_sync(0xffffffffu, rs[1], off);
        }
        if (sx == 0) {
#pragma unroll
            for (int i = 0; i < 2; i++) {
                int r = 2 * sy + i;
                row_l[r] = row_l[r] * row_corr[r] + rs[i];
            }
        }
        __syncthreads();

        float corr[4];
#pragma unroll
        for (int i = 0; i < 4; i++) corr[i] = row_corr[4 * ty + i];
#pragma unroll
        for (int i = 0; i < 4; i++)
#pragma unroll
            for (int j = 0; j < 4; j++) o[i][j] *= corr[i];

#pragma unroll
        for (int k4 = 0; k4 < 8; k4++) {
            float p[4][4];
#pragma unroll
            for (int i = 0; i < 4; i++) {
                float4 t = *(const float4*)&Ps[4 * ty + i][k4 * 4];
                p[i][0] = t.x; p[i][1] = t.y; p[i][2] = t.z; p[i][3] = t.w;
            }
#pragma unroll
            for (int u = 0; u < 4; u++) {
                float4 t = *(const float4*)&Vs[k4 * 4 + u][tx * 4];
                float vv[4] = {t.x, t.y, t.z, t.w};
#pragma unroll
                for (int i = 0; i < 4; i++)
#pragma unroll
                    for (int j = 0; j < 4; j++)
                        o[i][j] = fmaf(p[i][u], vv[j], o[i][j]);
            }
        }
        __syncthreads();
    }

    float inv[4];
#pragma unroll
    for (int i = 0; i < 4; i++) inv[i] = 1.f / row_l[4 * ty + i];

    float* dst = g_ctx + ((size_t)(b * S_ + qt * AQ)) * D_ + h * DK_;
#pragma unroll
    for (int i = 0; i < 4; i++) {
        float4 ov = make_float4(o[i][0] * inv[i], o[i][1] * inv[i],
                                o[i][2] * inv[i], o[i][3] * inv[i]);
        *(float4*)(dst + (size_t)(4 * ty + i) * D_ + tx * 4) = ov;
    }
}

// ==================== launch ====================
extern "C" void kernel_launch(void* const* d_in, const int* in_sizes, int n_in,
                              void* d_out, int out_size) {
    const float* query = (const float*)d_in[0];
    const float* key   = (const float*)d_in[1];
    const float* value = (const float*)d_in[2];
    const int*   mask  = (const int*)d_in[3];
    const float* Wq = (const float*)d_in[4];
    const float* bq = (const float*)d_in[5];
    const float* Wk = (const float*)d_in[6];
    const float* bk = (const float*)d_in[7];
    const float* Wv = (const float*)d_in[8];
    const float* bv = (const float*)d_in[9];
    const float* Wo = (const float*)d_in[10];
    const float* bo = (const float*)d_in[11];
    float* out = (float*)d_out;

    cudaFuncSetAttribute(gemm_mma_kernel<0>, cudaFuncAttributeMaxDynamicSharedMemorySize, GSMEM);
    cudaFuncSetAttribute(gemm_mma_kernel<1>, cudaFuncAttributeMaxDynamicSharedMemorySize, GSMEM);
    cudaFuncSetAttribute(gemm_mma_kernel<2>, cudaFuncAttributeMaxDynamicSharedMemorySize, GSMEM);
    cudaFuncSetAttribute(gemm_mma_kernel<3>, cudaFuncAttributeMaxDynamicSharedMemorySize, GSMEM);

    // weight transpose + bf16 split
    dim3 wtg(D_ / 32, D_ / 32), wtb(32, 8);
    conv_wT_kernel<<<wtg, wtb>>>(Wq, 0);
    conv_wT_kernel<<<wtg, wtb>>>(Wk, 1);
    conv_wT_kernel<<<wtg, wtb>>>(Wv, 2);
    conv_wT_kernel<<<wtg, wtb>>>(Wo, 3);

    // activation bf16 split
    const int nblk = (M_ * D_ / 4) / 256;    // 4096
    conv_hl_kernel<<<nblk, 256>>>(query, 0);
    conv_hl_kernel<<<nblk, 256>>>(key, 1);
    conv_hl_kernel<<<nblk, 256>>>(value, 2);

    // Q/K/V projections on tensor cores (mma.sync)
    dim3 gg(D_ / BN, M_ / BM);               // (8, 32)
    gemm_mma_kernel<0><<<gg, 256, GSMEM>>>(bq, nullptr);
    gemm_mma_kernel<1><<<gg, 256, GSMEM>>>(bk, nullptr);
    gemm_mma_kernel<2><<<gg, 256, GSMEM>>>(bv, nullptr);

    // attention (fp32 SIMT)
    dim3 ga(S_ / AQ, B_ * H_);               // (32, 32)
    attn_kernel<<<ga, 256>>>(mask);

    // ctx bf16 split + output projection
    conv_hl_kernel<<<nblk, 256>>>(nullptr, 3);
    gemm_mma_kernel<3><<<gg, 256, GSMEM>>>(bo, out);
}

// round 7
// speedup vs baseline: 3.0904x; 2.2814x over previous
#include <cuda_runtime.h>
#include <cuda_bf16.h>
#include <cstdint>

// Problem constants (match reference setup_inputs)
constexpr int B_ = 2;
constexpr int H_ = 16;
constexpr int S_ = 2048;
constexpr int D_ = 1024;     // d_model
constexpr int DK_ = 64;      // head dim
constexpr int M_ = B_ * S_;  // 4096 rows in all GEMMs

// Q pre-scale: 1/sqrt(Dk) * log2(e) so softmax uses exp2 directly
#define QSCALE 0.18033688011112042f
#define NEGB  (-1.0e8f)

// ==================== PTX helpers (sm_80-baseline only) ====================
__device__ __forceinline__ uint32_t smem_to_u32(const void* p) {
    uint32_t a;
    asm("{ .reg .u64 t; cvta.to.shared.u64 t, %1; cvt.u32.u64 %0, t; }" : "=r"(a) : "l"(p));
    return a;
}
__device__ __forceinline__ void cp_async16(uint32_t dst, const void* src) {
    asm volatile("cp.async.cg.shared.global [%0], [%1], 16;" :: "r"(dst), "l"(src));
}
__device__ __forceinline__ void cp_commit() {
    asm volatile("cp.async.commit_group;");
}
template <int N>
__device__ __forceinline__ void cp_wait() {
    asm volatile("cp.async.wait_group %0;" :: "n"(N));
}
__device__ __forceinline__ void ldm_x4(uint32_t& r0, uint32_t& r1, uint32_t& r2, uint32_t& r3,
                                       uint32_t addr) {
    asm volatile("ldmatrix.sync.aligned.m8n8.x4.shared.b16 {%0,%1,%2,%3}, [%4];"
                 : "=r"(r0), "=r"(r1), "=r"(r2), "=r"(r3) : "r"(addr));
}
__device__ __forceinline__ void ldm_x4_t(uint32_t& r0, uint32_t& r1, uint32_t& r2, uint32_t& r3,
                                         uint32_t addr) {
    asm volatile("ldmatrix.sync.aligned.m8n8.x4.trans.shared.b16 {%0,%1,%2,%3}, [%4];"
                 : "=r"(r0), "=r"(r1), "=r"(r2), "=r"(r3) : "r"(addr));
}
__device__ __forceinline__ void mma_bf16(float* c, const uint32_t* a, const uint32_t* b) {
    asm volatile(
        "mma.sync.aligned.m16n8k16.row.col.f32.bf16.bf16.f32 "
        "{%0,%1,%2,%3}, {%4,%5,%6,%7}, {%8,%9}, {%0,%1,%2,%3};"
        : "+f"(c[0]), "+f"(c[1]), "+f"(c[2]), "+f"(c[3])
        : "r"(a[0]), "r"(a[1]), "r"(a[2]), "r"(a[3]), "r"(b[0]), "r"(b[1]));
}
__device__ __forceinline__ float ex2(float x) {
    float y;
    asm("ex2.approx.f32 %0, %1;" : "=f"(y) : "f"(x));
    return y;
}
// split (a,b) fp32 pair into packed bf16x2 hi + lo
__device__ __forceinline__ void split2(float a, float b, uint32_t& hi, uint32_t& lo) {
    __nv_bfloat162 h = __floats2bfloat162_rn(a, b);
    float2 hf = __bfloat1622float2(h);
    __nv_bfloat162 l = __floats2bfloat162_rn(a - hf.x, b - hf.y);
    hi = *(uint32_t*)&h;
    lo = *(uint32_t*)&l;
}

// -------------------- device scratch (no allocations allowed) --------------------
// bf16 hi/lo Q (pre-scaled), K, V in head-split layout [B,H,S,64]
__device__ __nv_bfloat16 g_Qh[(size_t)B_ * H_ * S_ * DK_];
__device__ __nv_bfloat16 g_Ql[(size_t)B_ * H_ * S_ * DK_];
__device__ __nv_bfloat16 g_Kh[(size_t)B_ * H_ * S_ * DK_];
__device__ __nv_bfloat16 g_Kl[(size_t)B_ * H_ * S_ * DK_];
__device__ __nv_bfloat16 g_Vh[(size_t)B_ * H_ * S_ * DK_];
__device__ __nv_bfloat16 g_Vl[(size_t)B_ * H_ * S_ * DK_];
// attention output (hi/lo bf16) [B,S,D]
__device__ __nv_bfloat16 g_ctxH[(size_t)M_ * D_];
__device__ __nv_bfloat16 g_ctxL[(size_t)M_ * D_];
// activation hi/lo splits for projections
__device__ __nv_bfloat16 g_actH[3][(size_t)M_ * D_];
__device__ __nv_bfloat16 g_actL[3][(size_t)M_ * D_];
// transposed weights [N,K] hi/lo
__device__ __nv_bfloat16 g_wTH[4][(size_t)D_ * D_];
__device__ __nv_bfloat16 g_wTL[4][(size_t)D_ * D_];

// ==================== conversion kernels ====================
__global__ __launch_bounds__(256) void conv_hl_kernel(const float* __restrict__ src, int which) {
    __nv_bfloat16* hi = g_actH[which];
    __nv_bfloat16* lo = g_actL[which];
    int i = blockIdx.x * blockDim.x + threadIdx.x;   // float4 index
    float4 v = ((const float4*)src)[i];
    float f[4] = {v.x, v.y, v.z, v.w};
    __nv_bfloat16 h[4], l[4];
#pragma unroll
    for (int j = 0; j < 4; j++) {
        h[j] = __float2bfloat16(f[j]);
        l[j] = __float2bfloat16(f[j] - __bfloat162float(h[j]));
    }
    ((__nv_bfloat162*)hi)[i * 2 + 0] = __nv_bfloat162(h[0], h[1]);
    ((__nv_bfloat162*)hi)[i * 2 + 1] = __nv_bfloat162(h[2], h[3]);
    ((__nv_bfloat162*)lo)[i * 2 + 0] = __nv_bfloat162(l[0], l[1]);
    ((__nv_bfloat162*)lo)[i * 2 + 1] = __nv_bfloat162(l[2], l[3]);
}

// W [K,N] fp32 -> transposed hi/lo bf16 [N,K]
__global__ __launch_bounds__(256) void conv_wT_kernel(const float* __restrict__ W, int which) {
    __shared__ float t[32][33];
    const int n0 = blockIdx.x * 32, k0 = blockIdx.y * 32;
    const int tx = threadIdx.x, ty = threadIdx.y;     // block (32,8)
#pragma unroll
    for (int r = 0; r < 32; r += 8)
        t[ty + r][tx] = W[(size_t)(k0 + ty + r) * D_ + n0 + tx];
    __syncthreads();
    __nv_bfloat16* hi = g_wTH[which];
    __nv_bfloat16* lo = g_wTL[which];
#pragma unroll
    for (int r = 0; r < 32; r += 8) {
        float v = t[tx][ty + r];
        __nv_bfloat16 h = __float2bfloat16(v);
        __nv_bfloat16 l = __float2bfloat16(v - __bfloat162float(h));
        size_t o = (size_t)(n0 + ty + r) * D_ + k0 + tx;
        hi[o] = h; lo[o] = l;
    }
}

// ==================== mma.sync GEMM (3x bf16 split) ====================
// C[4096,1024] = A @ W + bias. CTA 128x128, BK=32, 8 warps (warp tile 32x64).
// TGT 0 -> Q (scaled, bf16 hi/lo), 1 -> K, 2 -> V, 3 -> fp32 out.
constexpr int BM = 128, BN = 128, BK = 32;
constexpr int TPAD = 40;
constexpr int TILE_B = 128 * TPAD * 2;
constexpr int STAGE_B = 4 * TILE_B;
constexpr int GSMEM = 2 * STAGE_B;
constexpr int NC = D_ / BK;

template <int TGT>
__global__ __launch_bounds__(256, 2) void gemm_mma_kernel(const float* __restrict__ bias,
                                                          float* __restrict__ outp) {
    extern __shared__ __align__(128) char sm[];
    const uint32_t smbase = smem_to_u32(sm);
    const int tid = threadIdx.x, wid = tid >> 5, lane = tid & 31;
    const int m0 = blockIdx.y * BM, n0 = blockIdx.x * BN;
    const int wm = (wid & 3) * 32, wn = (wid >> 2) * 64;

    const __nv_bfloat16* Ah;
    const __nv_bfloat16* Al;
    if constexpr (TGT < 3) { Ah = g_actH[TGT]; Al = g_actL[TGT]; }
    else                   { Ah = g_ctxH;      Al = g_ctxL;      }
    const __nv_bfloat16* Bh = g_wTH[TGT];
    const __nv_bfloat16* Bl = g_wTL[TGT];

    float acc[2][8][4];
#pragma unroll
    for (int i = 0; i < 2; i++)
#pragma unroll
        for (int j = 0; j < 8; j++)
#pragma unroll
            for (int q = 0; q < 4; q++) acc[i][j][q] = 0.f;

    auto issue_load = [&](int c) {
        const int s = c & 1, k0 = c * BK;
        const uint32_t st = smbase + s * STAGE_B;
#pragma unroll
        for (int t = 0; t < 8; t++) {
            int i = tid + t * 256;
            int tile = i >> 9, rem = i & 511, row = rem >> 2, cc = rem & 3;
            const __nv_bfloat16* src;
            if (tile == 0)      src = Ah + (size_t)(m0 + row) * D_ + k0 + cc * 8;
            else if (tile == 1) src = Al + (size_t)(m0 + row) * D_ + k0 + cc * 8;
            else if (tile == 2) src = Bh + (size_t)(n0 + row) * D_ + k0 + cc * 8;
            else                src = Bl + (size_t)(n0 + row) * D_ + k0 + cc * 8;
            cp_async16(st + tile * TILE_B + (row * TPAD + cc * 8) * 2, src);
        }
        cp_commit();
    };

    issue_load(0);

    for (int c = 0; c < NC; c++) {
        if (c + 1 < NC) { issue_load(c + 1); cp_wait<1>(); }
        else            { cp_wait<0>(); }
        __syncthreads();

        const uint32_t st = smbase + (c & 1) * STAGE_B;
#pragma unroll
        for (int k16 = 0; k16 < BK; k16 += 16) {
            uint32_t a_hi[2][4], a_lo[2][4];
            const int arow = wm + (lane & 15);
            const int acol = k16 + (lane >> 4) * 8;
#pragma unroll
            for (int i = 0; i < 2; i++) {
                uint32_t off = ((arow + i * 16) * TPAD + acol) * 2;
                ldm_x4(a_hi[i][0], a_hi[i][1], a_hi[i][2], a_hi[i][3], st + off);
                ldm_x4(a_lo[i][0], a_lo[i][1], a_lo[i][2], a_lo[i][3], st + TILE_B + off);
            }
            const int brow_base = wn + ((lane >> 4) & 1) * 8 + (lane & 7);
            const int bcol = k16 + ((lane >> 3) & 1) * 8;
#pragma unroll
            for (int jj = 0; jj < 4; jj++) {
                uint32_t off = ((brow_base + jj * 16) * TPAD + bcol) * 2;
                uint32_t bh[4], bl[4];
                ldm_x4(bh[0], bh[1], bh[2], bh[3], st + 2 * TILE_B + off);
                ldm_x4(bl[0], bl[1], bl[2], bl[3], st + 3 * TILE_B + off);
#pragma unroll
                for (int i = 0; i < 2; i++) {
                    mma_bf16(acc[i][2 * jj + 0], a_hi[i], bh + 0);
                    mma_bf16(acc[i][2 * jj + 0], a_lo[i], bh + 0);
                    mma_bf16(acc[i][2 * jj + 0], a_hi[i], bl + 0);
                    mma_bf16(acc[i][2 * jj + 1], a_hi[i], bh + 2);
                    mma_bf16(acc[i][2 * jj + 1], a_lo[i], bh + 2);
                    mma_bf16(acc[i][2 * jj + 1], a_hi[i], bl + 2);
                }
            }
        }
        __syncthreads();
    }

    // ---- epilogue ----
    const int tr = lane >> 2, tc = (lane & 3) * 2;
#pragma unroll
    for (int i = 0; i < 2; i++) {
#pragma unroll
        for (int hh = 0; hh < 2; hh++) {
            const int m = m0 + wm + i * 16 + tr + hh * 8;
            if constexpr (TGT < 3) {
                __nv_bfloat16* Hdst;
                __nv_bfloat16* Ldst;
                if constexpr (TGT == 0)      { Hdst = g_Qh; Ldst = g_Ql; }
                else if constexpr (TGT == 1) { Hdst = g_Kh; Ldst = g_Kl; }
                else                         { Hdst = g_Vh; Ldst = g_Vl; }
                const int hd = (n0 + wn) >> 6;
                const int b = m >> 11, sq = m & (S_ - 1);
                const size_t rowbase = ((size_t)((b * H_ + hd) * S_ + sq)) * DK_;
#pragma unroll
                for (int j = 0; j < 8; j++) {
                    const int n = n0 + wn + j * 8 + tc;
                    float vx = acc[i][j][hh * 2 + 0] + bias[n];
                    float vy = acc[i][j][hh * 2 + 1] + bias[n + 1];
                    if constexpr (TGT == 0) { vx *= QSCALE; vy *= QSCALE; }
                    uint32_t phi, plo;
                    split2(vx, vy, phi, plo);
                    *(uint32_t*)&Hdst[rowbase + j * 8 + tc] = phi;
                    *(uint32_t*)&Ldst[rowbase + j * 8 + tc] = plo;
                }
            } else {
                float* p = outp + (size_t)m * D_ + n0 + wn + tc;
#pragma unroll
                for (int j = 0; j < 8; j++) {
                    const int n = n0 + wn + j * 8 + tc;
                    float2 o;
                    o.x = acc[i][j][hh * 2 + 0] + bias[n];
                    o.y = acc[i][j][hh * 2 + 1] + bias[n + 1];
                    *(float2*)(p + j * 8) = o;
                }
            }
        }
    }
}

// ==================== mma.sync flash attention ====================
// CTA: 128 q-rows, 8 warps (16 q-rows each, full 128-key tile per warp).
// K/V hi/lo double-buffered via cp.async. Everything split-precision.
constexpr int KPAD = 72;                          // padded row (bf16) for conflict-free ldmatrix
constexpr int ATILE = 128 * KPAD * 2;             // 18432 B per [128 x 64] tile
constexpr int ASTAGE = 4 * ATILE;                 // Khi,Klo,Vhi,Vlo
constexpr int AQBYTES = 2 * ATILE;                // Qhi,Qlo
constexpr int ASMEM = AQBYTES + 2 * ASTAGE;       // 184320 B

__global__ __launch_bounds__(256, 1) void attn_mma_kernel(const int* __restrict__ mask) {
    extern __shared__ __align__(128) char smem_raw[];
    const uint32_t smbase = smem_to_u32(smem_raw);
    const int tid = threadIdx.x, wid = tid >> 5, lane = tid & 31;
    const int bh = blockIdx.y, b = bh >> 4, h = bh & 15;
    const int q0 = blockIdx.x * 128;

    const size_t hb = (size_t)bh * S_ * DK_;
    const __nv_bfloat16* Qhg = g_Qh + hb;
    const __nv_bfloat16* Qlg = g_Ql + hb;
    const __nv_bfloat16* Khg = g_Kh + hb;
    const __nv_bfloat16* Klg = g_Kl + hb;
    const __nv_bfloat16* Vhg = g_Vh + hb;
    const __nv_bfloat16* Vlg = g_Vl + hb;

    // ---- issue Q tile loads (hi/lo) ----
#pragma unroll
    for (int it = 0; it < 8; it++) {
        int flat = tid + it * 256;
        int tile = flat >> 10, rem = flat & 1023;
        int row = rem >> 3, c8 = rem & 7;
        const __nv_bfloat16* src = (tile == 0 ? Qhg : Qlg) + (size_t)(q0 + row) * DK_ + c8 * 8;
        cp_async16(smbase + tile * ATILE + row * (KPAD * 2) + c8 * 16, src);
    }
    cp_commit();

    auto issue_stage = [&](int t) {
        const int k0t = t * 128;
        const uint32_t st = smbase + AQBYTES + (t & 1) * ASTAGE;
#pragma unroll
        for (int it = 0; it < 16; it++) {
            int flat = tid + it * 256;
            int tile = flat >> 10, rem = flat & 1023;
            int row = rem >> 3, c8 = rem & 7;
            const __nv_bfloat16* src;
            if (tile == 0)      src = Khg + (size_t)(k0t + row) * DK_ + c8 * 8;
            else if (tile == 1) src = Klg + (size_t)(k0t + row) * DK_ + c8 * 8;
            else if (tile == 2) src = Vhg + (size_t)(k0t + row) * DK_ + c8 * 8;
            else                src = Vlg + (size_t)(k0t + row) * DK_ + c8 * 8;
            cp_async16(st + tile * ATILE + row * (KPAD * 2) + c8 * 16, src);
        }
        cp_commit();
    };

    issue_stage(0);

    // per-thread state
    uint32_t qh[4][4], ql[4][4];     // Q A-frags (loaded after first wait)
    float o[8][4];                   // O accumulator: 8 d-ntiles x 4
#pragma unroll
    for (int i = 0; i < 8; i++)
#pragma unroll
        for (int j = 0; j < 4; j++) o[i][j] = 0.f;
    float m0 = -1e30f, m1 = -1e30f, l0 = 0.f, l1 = 0.f;

    const int tr = lane >> 2, tc2 = (lane & 3) * 2;

#pragma unroll 1
    for (int t = 0; t < S_ / 128; t++) {
        if (t + 1 < S_ / 128) { issue_stage(t + 1); cp_wait<1>(); }
        else                  { cp_wait<0>(); }
        __syncthreads();

        if (t == 0) {
            // load Q fragments once (Q smem is ready after first wait)
            const int arow = wid * 16 + (lane & 15);
            const int acol = (lane >> 4) * 8;
#pragma unroll
            for (int kt = 0; kt < 4; kt++) {
                uint32_t off = (arow * KPAD + kt * 16 + acol) * 2;
                ldm_x4(qh[kt][0], qh[kt][1], qh[kt][2], qh[kt][3], smbase + off);
                ldm_x4(ql[kt][0], ql[kt][1], ql[kt][2], ql[kt][3], smbase + ATILE + off);
            }
        }

        const uint32_t kb = smbase + AQBYTES + (t & 1) * ASTAGE;

        // ---- QK^T: scores [16 q x 128 k] per warp ----
        float sc[16][4];
#pragma unroll
        for (int i = 0; i < 16; i++)
#pragma unroll
            for (int j = 0; j < 4; j++) sc[i][j] = 0.f;

#pragma unroll
        for (int kt = 0; kt < 4; kt++) {
            const int brow = ((lane >> 4) & 1) * 8 + (lane & 7);
            const int bcol = kt * 16 + ((lane >> 3) & 1) * 8;
#pragma unroll
            for (int g = 0; g < 8; g++) {
                uint32_t off = ((g * 16 + brow) * KPAD + bcol) * 2;
                uint32_t bhv[4], blv[4];
                ldm_x4(bhv[0], bhv[1], bhv[2], bhv[3], kb + off);
                ldm_x4(blv[0], blv[1], blv[2], blv[3], kb + ATILE + off);
                mma_bf16(sc[2 * g + 0], qh[kt], bhv + 0);
                mma_bf16(sc[2 * g + 0], ql[kt], bhv + 0);
                mma_bf16(sc[2 * g + 0], qh[kt], blv + 0);
                mma_bf16(sc[2 * g + 1], qh[kt], bhv + 2);
                mma_bf16(sc[2 * g + 1], ql[kt], bhv + 2);
                mma_bf16(sc[2 * g + 1], qh[kt], blv + 2);
            }
        }

        // ---- mask + online softmax ----
        const int2* mrow2 = (const int2*)(mask + b * S_ + t * 128);
        float mx0 = -3.4e38f, mx1 = -3.4e38f;
#pragma unroll
        for (int nt = 0; nt < 16; nt++) {
            int2 mv = mrow2[nt * 4 + (lane & 3)];
            if (mv.x == 0) { sc[nt][0] += NEGB; sc[nt][2] += NEGB; }
            if (mv.y == 0) { sc[nt][1] += NEGB; sc[nt][3] += NEGB; }
            mx0 = fmaxf(mx0, fmaxf(sc[nt][0], sc[nt][1]));
            mx1 = fmaxf(mx1, fmaxf(sc[nt][2], sc[nt][3]));
        }
        mx0 = fmaxf(mx0, __shfl_xor_sync(0xffffffffu, mx0, 1));
        mx0 = fmaxf(mx0, __shfl_xor_sync(0xffffffffu, mx0, 2));
        mx1 = fmaxf(mx1, __shfl_xor_sync(0xffffffffu, mx1, 1));
        mx1 = fmaxf(mx1, __shfl_xor_sync(0xffffffffu, mx1, 2));

        float m0n = fmaxf(m0, mx0), m1n = fmaxf(m1, mx1);
        float c0 = ex2(m0 - m0n), c1 = ex2(m1 - m1n);
        m0 = m0n; m1 = m1n;

        float sum0 = 0.f, sum1 = 0.f;
#pragma unroll
        for (int nt = 0; nt < 16; nt++) {
            sc[nt][0] = ex2(sc[nt][0] - m0n);
            sc[nt][1] = ex2(sc[nt][1] - m0n);
            sc[nt][2] = ex2(sc[nt][2] - m1n);
            sc[nt][3] = ex2(sc[nt][3] - m1n);
            sum0 += sc[nt][0] + sc[nt][1];
            sum1 += sc[nt][2] + sc[nt][3];
        }
        sum0 += __shfl_xor_sync(0xffffffffu, sum0, 1);
        sum0 += __shfl_xor_sync(0xffffffffu, sum0, 2);
        sum1 += __shfl_xor_sync(0xffffffffu, sum1, 1);
        sum1 += __shfl_xor_sync(0xffffffffu, sum1, 2);
        l0 = l0 * c0 + sum0;
        l1 = l1 * c1 + sum1;

        // rescale O
#pragma unroll
        for (int i = 0; i < 8; i++) {
            o[i][0] *= c0; o[i][1] *= c0;
            o[i][2] *= c1; o[i][3] *= c1;
        }

        // ---- P @ V (split P, split V via ldmatrix.trans) ----
#pragma unroll
        for (int kk = 0; kk < 8; kk++) {
            uint32_t ph[4], pl[4];
            split2(sc[2 * kk + 0][0], sc[2 * kk + 0][1], ph[0], pl[0]);
            split2(sc[2 * kk + 0][2], sc[2 * kk + 0][3], ph[1], pl[1]);
            split2(sc[2 * kk + 1][0], sc[2 * kk + 1][1], ph[2], pl[2]);
            split2(sc[2 * kk + 1][2], sc[2 * kk + 1][3], ph[3], pl[3]);

            const int krow = kk * 16 + ((lane >> 3) & 1) * 8 + (lane & 7);
            const int dcol = ((lane >> 4) & 1) * 8;
#pragma unroll
            for (int g = 0; g < 4; g++) {
                uint32_t off = (krow * KPAD + g * 16 + dcol) * 2;
                uint32_t bhv[4], blv[4];
                ldm_x4_t(bhv[0], bhv[1], bhv[2], bhv[3], kb + 2 * ATILE + off);
                ldm_x4_t(blv[0], blv[1], blv[2], blv[3], kb + 3 * ATILE + off);
                mma_bf16(o[2 * g + 0], ph, bhv + 0);
                mma_bf16(o[2 * g + 0], pl, bhv + 0);
                mma_bf16(o[2 * g + 0], ph, blv + 0);
                mma_bf16(o[2 * g + 1], ph, bhv + 2);
                mma_bf16(o[2 * g + 1], pl, bhv + 2);
                mma_bf16(o[2 * g + 1], ph, blv + 2);
            }
        }
        __syncthreads();
    }

    // ---- epilogue: O / l -> bf16 hi/lo ctx ----
    const float inv0 = 1.f / l0, inv1 = 1.f / l1;
    const int r0 = q0 + wid * 16 + tr;
    const size_t base0 = ((size_t)(b * S_ + r0)) * D_ + h * DK_;
    const size_t base1 = ((size_t)(b * S_ + r0 + 8)) * D_ + h * DK_;
#pragma unroll
    for (int nt = 0; nt < 8; nt++) {
        const int d0 = nt * 8 + tc2;
        uint32_t phi, plo;
        split2(o[nt][0] * inv0, o[nt][1] * inv0, phi, plo);
        *(uint32_t*)&g_ctxH[base0 + d0] = phi;
        *(uint32_t*)&g_ctxL[base0 + d0] = plo;
        split2(o[nt][2] * inv1, o[nt][3] * inv1, phi, plo);
        *(uint32_t*)&g_ctxH[base1 + d0] = phi;
        *(uint32_t*)&g_ctxL[base1 + d0] = plo;
    }
}

// ==================== launch ====================
extern "C" void kernel_launch(void* const* d_in, const int* in_sizes, int n_in,
                              void* d_out, int out_size) {
    const float* query = (const float*)d_in[0];
    const float* key   = (const float*)d_in[1];
    const float* value = (const float*)d_in[2];
    const int*   mask  = (const int*)d_in[3];
    const float* Wq = (const float*)d_in[4];
    const float* bq = (const float*)d_in[5];
    const float* Wk = (const float*)d_in[6];
    const float* bk = (const float*)d_in[7];
    const float* Wv = (const float*)d_in[8];
    const float* bv = (const float*)d_in[9];
    const float* Wo = (const float*)d_in[10];
    const float* bo = (const float*)d_in[11];
    float* out = (float*)d_out;

    cudaFuncSetAttribute(gemm_mma_kernel<0>, cudaFuncAttributeMaxDynamicSharedMemorySize, GSMEM);
    cudaFuncSetAttribute(gemm_mma_kernel<1>, cudaFuncAttributeMaxDynamicSharedMemorySize, GSMEM);
    cudaFuncSetAttribute(gemm_mma_kernel<2>, cudaFuncAttributeMaxDynamicSharedMemorySize, GSMEM);
    cudaFuncSetAttribute(gemm_mma_kernel<3>, cudaFuncAttributeMaxDynamicSharedMemorySize, GSMEM);
    cudaFuncSetAttribute(attn_mma_kernel, cudaFuncAttributeMaxDynamicSharedMemorySize, ASMEM);

    // weight transpose + bf16 split
    dim3 wtg(D_ / 32, D_ / 32), wtb(32, 8);
    conv_wT_kernel<<<wtg, wtb>>>(Wq, 0);
    conv_wT_kernel<<<wtg, wtb>>>(Wk, 1);
    conv_wT_kernel<<<wtg, wtb>>>(Wv, 2);
    conv_wT_kernel<<<wtg, wtb>>>(Wo, 3);

    // activation bf16 split
    const int nblk = (M_ * D_ / 4) / 256;    // 4096
    conv_hl_kernel<<<nblk, 256>>>(query, 0);
    conv_hl_kernel<<<nblk, 256>>>(key, 1);
    conv_hl_kernel<<<nblk, 256>>>(value, 2);

    // Q/K/V projections -> bf16 hi/lo head-split
    dim3 gg(D_ / BN, M_ / BM);               // (8, 32)
    gemm_mma_kernel<0><<<gg, 256, GSMEM>>>(bq, nullptr);
    gemm_mma_kernel<1><<<gg, 256, GSMEM>>>(bk, nullptr);
    gemm_mma_kernel<2><<<gg, 256, GSMEM>>>(bv, nullptr);

    // flash attention on tensor cores
    dim3 ga(S_ / 128, B_ * H_);              // (16, 32)
    attn_mma_kernel<<<ga, 256, ASMEM>>>(mask);

    // output projection (reads ctx hi/lo written by attention)
    gemm_mma_kernel<3><<<gg, 256, GSMEM>>>(bo, out);
}